// round 14
// baseline (speedup 1.0000x reference)
#include <cuda_runtime.h>
#include <cuda_fp16.h>
#include <math.h>
#include <stdint.h>

#define HDIM    4096
#define EXP     64
#define TOPK    8
#define CTAROWS 64
#define THREADS 256
#define KC      32
#define NCHUNK  (HDIM / KC)      // 128
#define FOLD    4
#define WSCALE  64.0f
#define WINV    (1.0f / 64.0f)

// SMEM: double-buffered A tiles (fp16x2, 64 rows x 32k, 80B stride) + bias.
#define OFF_BIAS 0
#define OFF_A    256
#define A_LVL    (CTAROWS * 80)          // 5120
#define A_STG    (2 * A_LVL)             // 10240
#define SMEM_SZ  (OFF_A + 2 * A_STG)     // 20736
#define OFF_LOG  OFF_A                   // 64*66*4 = 16896 fits in 20480
#define LOGSTR   66

// W (x64) in B-fragment order: [chunk][ks][lvb(2)][nt(8)][lane(32)] -> uint2{b0,b1}
#define NFRAG (NCHUNK * 2 * 2 * 8 * 32)
__device__ uint2 g_wfrag[NFRAG];

// ---------------- helpers ----------------
static __device__ __forceinline__ uint32_t smem_u32(const void* p) {
    uint32_t a;
    asm("{ .reg .u64 t; cvta.to.shared.u64 t, %1; cvt.u32.u64 %0, t; }"
        : "=r"(a) : "l"(p));
    return a;
}
// split fp32 pair -> 2 packed fp16x2 words (a ~= h0 + h1, residual ~2^-22)
static __device__ __forceinline__ void split2h(float a0, float a1,
                                               uint32_t& u0, uint32_t& u1) {
    __half h0x = __float2half_rn(a0), h0y = __float2half_rn(a1);
    float r0 = a0 - __half2float(h0x);
    float r1 = a1 - __half2float(h0y);
    __half h1x = __float2half_rn(r0), h1y = __float2half_rn(r1);
    __half2 p0 = __halves2half2(h0x, h0y);
    __half2 p1 = __halves2half2(h1x, h1y);
    u0 = *reinterpret_cast<uint32_t*>(&p0);
    u1 = *reinterpret_cast<uint32_t*>(&p1);
}
static __device__ __forceinline__ void ldsm4(uint32_t* r, uint32_t addr) {
    asm volatile("ldmatrix.sync.aligned.m8n8.x4.shared.b16 {%0,%1,%2,%3}, [%4];"
                 : "=r"(r[0]), "=r"(r[1]), "=r"(r[2]), "=r"(r[3]) : "r"(addr));
}
static __device__ __forceinline__ void mma16816(float* c, const uint32_t* a,
                                                const uint32_t* b) {
    asm volatile(
        "mma.sync.aligned.m16n8k16.row.col.f32.f16.f16.f32 "
        "{%0,%1,%2,%3}, {%4,%5,%6,%7}, {%8,%9}, {%0,%1,%2,%3};"
        : "+f"(c[0]), "+f"(c[1]), "+f"(c[2]), "+f"(c[3])
        : "r"(a[0]), "r"(a[1]), "r"(a[2]), "r"(a[3]), "r"(b[0]), "r"(b[1]));
}

// ---------------- W repack: fp32*64 -> fp16x2 B-fragments ----------------
__global__ void wfrag_kernel(const float* __restrict__ W) {
    int idx = blockIdx.x * blockDim.x + threadIdx.x;
    if (idx >= NFRAG) return;
    int lane = idx & 31;
    int nt   = (idx >> 5) & 7;
    int t    = idx >> 8;
    int lvb  = t & 1;
    int ks   = (t >> 1) & 1;
    int ch   = t >> 2;
    int e = nt * 8 + (lane >> 2);
    int k = ch * KC + ks * 16 + (lane & 3) * 2;
    const float* w = W + (long long)e * HDIM + k;
    uint32_t u0a, u1a, u0b, u1b;
    split2h(w[0] * WSCALE, w[1] * WSCALE, u0a, u1a);
    split2h(w[8] * WSCALE, w[9] * WSCALE, u0b, u1b);
    uint2 v;
    v.x = lvb ? u1a : u0a;
    v.y = lvb ? u1b : u0b;
    g_wfrag[idx] = v;
}

// ---------------- fused gating ----------------
__global__ __launch_bounds__(THREADS, 2)
void gating_fused(const float* __restrict__ x, const float* __restrict__ b,
                  float* __restrict__ sparse, float* __restrict__ idxf,
                  float* __restrict__ gate)
{
    extern __shared__ char smem[];
    const uint32_t sb = smem_u32(smem);
    const int tid  = threadIdx.x;
    const int warp = tid >> 5;
    const int lane = tid & 31;
    const int rg = warp & 1;      // rows rg*32..+32
    const int eg = warp >> 1;     // experts eg*16..+16 (nt tiles 2eg, 2eg+1)
    const long long row_base = (long long)blockIdx.x * CTAROWS;

    if (tid < EXP) ((float*)(smem + OFF_BIAS))[tid] = b[tid];

    const float4* __restrict__ x4 = reinterpret_cast<const float4*>(x);

    const uint32_t a_lane = (uint32_t)((lane & 15) * 80 + (lane >> 4) * 16);
    const uint32_t a_base = sb + OFF_A + (uint32_t)rg * (32 * 80) + a_lane;

    float acc[16], sum[16];
#pragma unroll
    for (int i = 0; i < 16; ++i) { acc[i] = 0.f; sum[i] = 0.f; }

    // ---- prologue: load + convert chunk 0 into stage 0 ----
    float4 xr[2];
#pragma unroll
    for (int j = 0; j < 2; ++j) {
        int f = j * 256 + tid, r = f >> 3, q = f & 7;
        xr[j] = x4[(row_base + r) * (HDIM / 4) + q];
    }
#pragma unroll
    for (int j = 0; j < 2; ++j) {
        int f = j * 256 + tid, r = f >> 3, q = f & 7;
        uint2 v0, v1;
        split2h(xr[j].x, xr[j].y, v0.x, v1.x);
        split2h(xr[j].z, xr[j].w, v0.y, v1.y);
        uint32_t so = (uint32_t)(r * 80 + q * 8);
        *(uint2*)(smem + OFF_A + 0 * A_LVL + so) = v0;
        *(uint2*)(smem + OFF_A + 1 * A_LVL + so) = v1;
    }

    // B fragment double buffer; preload (chunk0, ks0, lvb0)
    uint2 bf[2][2];
    {
        const uint2* p0 = g_wfrag + (long long)(eg * 2) * 32 + lane;
        bf[0][0] = p0[0];
        bf[0][1] = p0[32];
    }
    int pp = 0;

    __syncthreads();

    for (int i = 0; i < NCHUNK; ++i) {
        const int stg = i & 1;
        const uint32_t a_st = a_base + (uint32_t)stg * A_STG;

        // ---- prefetch x for chunk i+1 ----
        if (i + 1 < NCHUNK) {
#pragma unroll
            for (int j = 0; j < 2; ++j) {
                int f = j * 256 + tid, r = f >> 3, q = f & 7;
                xr[j] = x4[(row_base + r) * (HDIM / 4) + (i + 1) * 8 + q];
            }
        }

        // ---- compute: per ks, 3 passes (b0c0, b1c0, b0c1) ----
#pragma unroll
        for (int ks = 0; ks < 2; ++ks) {
            uint32_t afr[2][2][4];
#pragma unroll
            for (int lv = 0; lv < 2; ++lv)
#pragma unroll
                for (int mt = 0; mt < 2; ++mt)
                    ldsm4(afr[lv][mt], a_st + lv * A_LVL + mt * (16 * 80) + ks * 32);

            // prefetch (i, ks, lvb=1)
            {
                const uint2* np = g_wfrag +
                    ((long long)(((i * 2 + ks) * 2 + 1) * 8 + eg * 2) * 32) + lane;
                bf[pp ^ 1][0] = np[0];
                bf[pp ^ 1][1] = np[32];
            }
            // passes with B level 0: A levels 0 and 1 (b0c0 + b1c0)
#pragma unroll
            for (int ap = 0; ap < 2; ++ap)
#pragma unroll
                for (int mt = 0; mt < 2; ++mt)
#pragma unroll
                    for (int nt = 0; nt < 2; ++nt)
                        mma16816(&acc[(mt * 2 + nt) * 4], afr[ap][mt],
                                 (const uint32_t*)&bf[pp][nt]);
            pp ^= 1;

            // prefetch next stage's lvb0: (i, ks+1) or (i+1, 0)
            {
                int nch = i, nks = ks + 1;
                if (nks == 2) { nks = 0; nch = (i + 1 < NCHUNK) ? i + 1 : i; }
                const uint2* np = g_wfrag +
                    ((long long)(((nch * 2 + nks) * 2 + 0) * 8 + eg * 2) * 32) + lane;
                bf[pp ^ 1][0] = np[0];
                bf[pp ^ 1][1] = np[32];
            }
            // pass with B level 1: A level 0 (b0c1)
#pragma unroll
            for (int mt = 0; mt < 2; ++mt)
#pragma unroll
                for (int nt = 0; nt < 2; ++nt)
                    mma16816(&acc[(mt * 2 + nt) * 4], afr[0][mt],
                             (const uint32_t*)&bf[pp][nt]);
            pp ^= 1;
        }

        // ---- convert chunk i+1 into the other stage ----
        if (i + 1 < NCHUNK) {
            const uint32_t dst = OFF_A + (uint32_t)(stg ^ 1) * A_STG;
#pragma unroll
            for (int j = 0; j < 2; ++j) {
                int f = j * 256 + tid, r = f >> 3, q = f & 7;
                uint2 v0, v1;
                split2h(xr[j].x, xr[j].y, v0.x, v1.x);
                split2h(xr[j].z, xr[j].w, v0.y, v1.y);
                uint32_t so = (uint32_t)(r * 80 + q * 8);
                *(uint2*)(smem + dst + 0 * A_LVL + so) = v0;
                *(uint2*)(smem + dst + 1 * A_LVL + so) = v1;
            }
        }

        // ---- fold into fp32 master (bounds HMMA chain bias) ----
        if ((i & (FOLD - 1)) == (FOLD - 1)) {
#pragma unroll
            for (int q = 0; q < 16; ++q) { sum[q] += acc[q]; acc[q] = 0.f; }
        }

        __syncthreads();
    }

    // ---- write logits to SMEM (undo W scale) ----
    {
        float* lg = (float*)(smem + OFF_LOG);
#pragma unroll
        for (int mt = 0; mt < 2; ++mt) {
            int r0 = rg * 32 + mt * 16 + (lane >> 2);
#pragma unroll
            for (int nt = 0; nt < 2; ++nt) {
                int col = eg * 16 + nt * 8 + (lane & 3) * 2;
                int a0 = (mt * 2 + nt) * 4;
                float t0 = (sum[a0 + 0] + acc[a0 + 0]) * WINV;
                float t1 = (sum[a0 + 1] + acc[a0 + 1]) * WINV;
                float t2 = (sum[a0 + 2] + acc[a0 + 2]) * WINV;
                float t3 = (sum[a0 + 3] + acc[a0 + 3]) * WINV;
                *(float2*)&lg[r0 * LOGSTR + col]       = make_float2(t0, t1);
                *(float2*)&lg[(r0 + 8) * LOGSTR + col] = make_float2(t2, t3);
            }
        }
    }
    __syncthreads();

    // ---- per-row epilogue: bias + gate + top-8 + masked softmax ----
    if (tid < CTAROWS) {
        const float* lg = (const float*)(smem + OFF_LOG) + tid * LOGSTR;
        const float* bs = (const float*)(smem + OFF_BIAS);
        float v[EXP];
#pragma unroll
        for (int c = 0; c < EXP; ++c) v[c] = lg[c] + bs[c];

        const long long grow = row_base + tid;
        float* gr = gate + grow * EXP;
#pragma unroll
        for (int c = 0; c < 16; ++c)
            ((float4*)gr)[c] = make_float4(v[4*c], v[4*c+1], v[4*c+2], v[4*c+3]);

        unsigned long long mask = 0ull;
        float sval[TOPK]; int sidx[TOPK];
        for (int t = 0; t < TOPK; ++t) {
            float best = -INFINITY; int bi = 0;
#pragma unroll
            for (int c = 0; c < EXP; ++c) {
                bool fr = !((mask >> c) & 1ull);
                if (fr && v[c] > best) { best = v[c]; bi = c; }   // tie -> lower idx
            }
            mask |= 1ull << bi;
            sval[t] = best; sidx[t] = bi;
        }
        float mx = sval[0], sumv = 0.f;
#pragma unroll
        for (int t = 0; t < TOPK; ++t) sumv += expf(sval[t] - mx);
        float inv = 1.0f / sumv;

        float* sr = sparse + grow * EXP;
#pragma unroll
        for (int c = 0; c < EXP; ++c) sr[c] = 0.0f;
        for (int t = 0; t < TOPK; ++t) {
            sr[sidx[t]] = expf(sval[t] - mx) * inv;
            idxf[grow * TOPK + t] = (float)sidx[t];
        }
    }
}

extern "C" void kernel_launch(void* const* d_in, const int* in_sizes, int n_in,
                              void* d_out, int out_size)
{
    const float* x = (const float*)d_in[0];
    const float* W = (const float*)d_in[1];
    const float* b = (const float*)d_in[2];

    const int M = in_sizes[0] / HDIM;     // 16384

    float* out    = (float*)d_out;
    float* sparse = out;
    float* idxf   = out + (long long)M * EXP;
    float* gate   = out + (long long)M * EXP + (long long)M * TOPK;

    wfrag_kernel<<<(NFRAG + 255) / 256, 256>>>(W);
    gating_fused<<<M / CTAROWS, THREADS, SMEM_SZ>>>(x, b, sparse, idxf, gate);
}

// round 15
// speedup vs baseline: 1.0185x; 1.0185x over previous
#include <cuda_runtime.h>
#include <cuda_fp16.h>
#include <math.h>
#include <stdint.h>

#define HDIM    4096
#define EXP     64
#define TOPK    8
#define CTAROWS 64
#define THREADS 256
#define KC      32
#define NCHUNK  (HDIM / KC)      // 128
#define FOLD    4
#define WSCALE  64.0f
#define WINV    (1.0f / 64.0f)

// SMEM: double-buffered A tiles (fp16x2, 64 rows x 32k, 80B stride) + bias.
#define OFF_BIAS 0
#define OFF_A    256
#define A_LVL    (CTAROWS * 80)          // 5120
#define A_STG    (2 * A_LVL)             // 10240
#define SMEM_SZ  (OFF_A + 2 * A_STG)     // 20736
#define OFF_LOG  OFF_A                   // 64*66*4 = 16896 fits in 20480
#define LOGSTR   66

// W (x64) in B-fragment order: [chunk][ks][lvb(2)][nt(8)][lane(32)] -> uint2{b0,b1}
#define NFRAG (NCHUNK * 2 * 2 * 8 * 32)
__device__ uint2 g_wfrag[NFRAG];

// ---------------- helpers ----------------
static __device__ __forceinline__ uint32_t smem_u32(const void* p) {
    uint32_t a;
    asm("{ .reg .u64 t; cvta.to.shared.u64 t, %1; cvt.u32.u64 %0, t; }"
        : "=r"(a) : "l"(p));
    return a;
}
// split fp32 pair -> 2 packed fp16x2 words (a ~= h0 + h1, residual ~2^-22)
static __device__ __forceinline__ void split2h(float a0, float a1,
                                               uint32_t& u0, uint32_t& u1) {
    __half h0x = __float2half_rn(a0), h0y = __float2half_rn(a1);
    float r0 = a0 - __half2float(h0x);
    float r1 = a1 - __half2float(h0y);
    __half h1x = __float2half_rn(r0), h1y = __float2half_rn(r1);
    __half2 p0 = __halves2half2(h0x, h0y);
    __half2 p1 = __halves2half2(h1x, h1y);
    u0 = *reinterpret_cast<uint32_t*>(&p0);
    u1 = *reinterpret_cast<uint32_t*>(&p1);
}
static __device__ __forceinline__ void ldsm4(uint32_t* r, uint32_t addr) {
    asm volatile("ldmatrix.sync.aligned.m8n8.x4.shared.b16 {%0,%1,%2,%3}, [%4];"
                 : "=r"(r[0]), "=r"(r[1]), "=r"(r[2]), "=r"(r[3]) : "r"(addr));
}
static __device__ __forceinline__ void mma16816(float* c, const uint32_t* a,
                                                const uint32_t* b) {
    asm volatile(
        "mma.sync.aligned.m16n8k16.row.col.f32.f16.f16.f32 "
        "{%0,%1,%2,%3}, {%4,%5,%6,%7}, {%8,%9}, {%0,%1,%2,%3};"
        : "+f"(c[0]), "+f"(c[1]), "+f"(c[2]), "+f"(c[3])
        : "r"(a[0]), "r"(a[1]), "r"(a[2]), "r"(a[3]), "r"(b[0]), "r"(b[1]));
}

// ---------------- W repack: fp32*64 -> fp16x2 B-fragments ----------------
__global__ void wfrag_kernel(const float* __restrict__ W) {
    int idx = blockIdx.x * blockDim.x + threadIdx.x;
    if (idx >= NFRAG) return;
    int lane = idx & 31;
    int nt   = (idx >> 5) & 7;
    int t    = idx >> 8;
    int lvb  = t & 1;
    int ks   = (t >> 1) & 1;
    int ch   = t >> 2;
    int e = nt * 8 + (lane >> 2);
    int k = ch * KC + ks * 16 + (lane & 3) * 2;
    const float* w = W + (long long)e * HDIM + k;
    uint32_t u0a, u1a, u0b, u1b;
    split2h(w[0] * WSCALE, w[1] * WSCALE, u0a, u1a);
    split2h(w[8] * WSCALE, w[9] * WSCALE, u0b, u1b);
    uint2 v;
    v.x = lvb ? u1a : u0a;
    v.y = lvb ? u1b : u0b;
    g_wfrag[idx] = v;
}

// ---------------- fused gating ----------------
__global__ __launch_bounds__(THREADS, 2)
void gating_fused(const float* __restrict__ x, const float* __restrict__ b,
                  float* __restrict__ sparse, float* __restrict__ idxf,
                  float* __restrict__ gate)
{
    extern __shared__ char smem[];
    const uint32_t sb = smem_u32(smem);
    const int tid  = threadIdx.x;
    const int warp = tid >> 5;
    const int lane = tid & 31;
    const int rg = warp & 1;      // rows rg*32..+32
    const int eg = warp >> 1;     // experts eg*16..+16 (nt tiles 2eg, 2eg+1)
    const long long row_base = (long long)blockIdx.x * CTAROWS;

    if (tid < EXP) ((float*)(smem + OFF_BIAS))[tid] = b[tid];

    const float4* __restrict__ x4 = reinterpret_cast<const float4*>(x);

    const uint32_t a_lane = (uint32_t)((lane & 15) * 80 + (lane >> 4) * 16);
    const uint32_t a_base = sb + OFF_A + (uint32_t)rg * (32 * 80) + a_lane;

    float acc[16], sum[16];
#pragma unroll
    for (int i = 0; i < 16; ++i) { acc[i] = 0.f; sum[i] = 0.f; }

    // ---- prologue: load + convert chunk 0 into stage 0 ----
    float4 xr[2];
#pragma unroll
    for (int j = 0; j < 2; ++j) {
        int f = j * 256 + tid, r = f >> 3, q = f & 7;
        xr[j] = x4[(row_base + r) * (HDIM / 4) + q];
    }
#pragma unroll
    for (int j = 0; j < 2; ++j) {
        int f = j * 256 + tid, r = f >> 3, q = f & 7;
        uint2 v0, v1;
        split2h(xr[j].x, xr[j].y, v0.x, v1.x);
        split2h(xr[j].z, xr[j].w, v0.y, v1.y);
        uint32_t so = (uint32_t)(r * 80 + q * 8);
        *(uint2*)(smem + OFF_A + 0 * A_LVL + so) = v0;
        *(uint2*)(smem + OFF_A + 1 * A_LVL + so) = v1;
    }

    // B fragment double buffer; preload (chunk0, ks0, lvb0)
    uint2 bf[2][2];
    {
        const uint2* p0 = g_wfrag + (long long)(eg * 2) * 32 + lane;
        bf[0][0] = p0[0];
        bf[0][1] = p0[32];
    }
    int pp = 0;

    __syncthreads();

    for (int i = 0; i < NCHUNK; ++i) {
        const int stg = i & 1;
        const uint32_t a_st = a_base + (uint32_t)stg * A_STG;

        // ---- prefetch x for chunk i+1 ----
        if (i + 1 < NCHUNK) {
#pragma unroll
            for (int j = 0; j < 2; ++j) {
                int f = j * 256 + tid, r = f >> 3, q = f & 7;
                xr[j] = x4[(row_base + r) * (HDIM / 4) + (i + 1) * 8 + q];
            }
        }

        // ---- compute: per ks, 3 passes (b0c0, b1c0, b0c1) ----
#pragma unroll
        for (int ks = 0; ks < 2; ++ks) {
            uint32_t afr[2][2][4];
#pragma unroll
            for (int lv = 0; lv < 2; ++lv)
#pragma unroll
                for (int mt = 0; mt < 2; ++mt)
                    ldsm4(afr[lv][mt], a_st + lv * A_LVL + mt * (16 * 80) + ks * 32);

            // prefetch (i, ks, lvb=1)
            {
                const uint2* np = g_wfrag +
                    ((long long)(((i * 2 + ks) * 2 + 1) * 8 + eg * 2) * 32) + lane;
                bf[pp ^ 1][0] = np[0];
                bf[pp ^ 1][1] = np[32];
            }
            // passes with B level 0: A levels 0 and 1 (b0c0 + b1c0)
#pragma unroll
            for (int ap = 0; ap < 2; ++ap)
#pragma unroll
                for (int mt = 0; mt < 2; ++mt)
#pragma unroll
                    for (int nt = 0; nt < 2; ++nt)
                        mma16816(&acc[(mt * 2 + nt) * 4], afr[ap][mt],
                                 (const uint32_t*)&bf[pp][nt]);
            pp ^= 1;

            // prefetch next stage's lvb0: (i, ks+1) or (i+1, 0)
            {
                int nch = i, nks = ks + 1;
                if (nks == 2) { nks = 0; nch = (i + 1 < NCHUNK) ? i + 1 : i; }
                const uint2* np = g_wfrag +
                    ((long long)(((nch * 2 + nks) * 2 + 0) * 8 + eg * 2) * 32) + lane;
                bf[pp ^ 1][0] = np[0];
                bf[pp ^ 1][1] = np[32];
            }
            // pass with B level 1: A level 0 (b0c1)
#pragma unroll
            for (int mt = 0; mt < 2; ++mt)
#pragma unroll
                for (int nt = 0; nt < 2; ++nt)
                    mma16816(&acc[(mt * 2 + nt) * 4], afr[0][mt],
                             (const uint32_t*)&bf[pp][nt]);
            pp ^= 1;
        }

        // ---- convert chunk i+1 into the other stage ----
        if (i + 1 < NCHUNK) {
            const uint32_t dst = OFF_A + (uint32_t)(stg ^ 1) * A_STG;
#pragma unroll
            for (int j = 0; j < 2; ++j) {
                int f = j * 256 + tid, r = f >> 3, q = f & 7;
                uint2 v0, v1;
                split2h(xr[j].x, xr[j].y, v0.x, v1.x);
                split2h(xr[j].z, xr[j].w, v0.y, v1.y);
                uint32_t so = (uint32_t)(r * 80 + q * 8);
                *(uint2*)(smem + dst + 0 * A_LVL + so) = v0;
                *(uint2*)(smem + dst + 1 * A_LVL + so) = v1;
            }
        }

        // ---- fold into fp32 master (bounds HMMA chain bias) ----
        if ((i & (FOLD - 1)) == (FOLD - 1)) {
#pragma unroll
            for (int q = 0; q < 16; ++q) { sum[q] += acc[q]; acc[q] = 0.f; }
        }

        __syncthreads();
    }

    // ---- write logits to SMEM (undo W scale) ----
    {
        float* lg = (float*)(smem + OFF_LOG);
#pragma unroll
        for (int mt = 0; mt < 2; ++mt) {
            int r0 = rg * 32 + mt * 16 + (lane >> 2);
#pragma unroll
            for (int nt = 0; nt < 2; ++nt) {
                int col = eg * 16 + nt * 8 + (lane & 3) * 2;
                int a0 = (mt * 2 + nt) * 4;
                float t0 = (sum[a0 + 0] + acc[a0 + 0]) * WINV;
                float t1 = (sum[a0 + 1] + acc[a0 + 1]) * WINV;
                float t2 = (sum[a0 + 2] + acc[a0 + 2]) * WINV;
                float t3 = (sum[a0 + 3] + acc[a0 + 3]) * WINV;
                *(float2*)&lg[r0 * LOGSTR + col]       = make_float2(t0, t1);
                *(float2*)&lg[(r0 + 8) * LOGSTR + col] = make_float2(t2, t3);
            }
        }
    }
    __syncthreads();

    // ---- per-row epilogue: bias + gate + top-8 + masked softmax ----
    if (tid < CTAROWS) {
        const float* lg = (const float*)(smem + OFF_LOG) + tid * LOGSTR;
        const float* bs = (const float*)(smem + OFF_BIAS);
        float v[EXP];
#pragma unroll
        for (int c = 0; c < EXP; ++c) v[c] = lg[c] + bs[c];

        const long long grow = row_base + tid;
        float* gr = gate + grow * EXP;
#pragma unroll
        for (int c = 0; c < 16; ++c)
            ((float4*)gr)[c] = make_float4(v[4*c], v[4*c+1], v[4*c+2], v[4*c+3]);

        unsigned long long mask = 0ull;
        float sval[TOPK]; int sidx[TOPK];
        for (int t = 0; t < TOPK; ++t) {
            float best = -INFINITY; int bi = 0;
#pragma unroll
            for (int c = 0; c < EXP; ++c) {
                bool fr = !((mask >> c) & 1ull);
                if (fr && v[c] > best) { best = v[c]; bi = c; }   // tie -> lower idx
            }
            mask |= 1ull << bi;
            sval[t] = best; sidx[t] = bi;
        }
        float mx = sval[0], sumv = 0.f;
#pragma unroll
        for (int t = 0; t < TOPK; ++t) sumv += expf(sval[t] - mx);
        float inv = 1.0f / sumv;

        float* sr = sparse + grow * EXP;
#pragma unroll
        for (int c = 0; c < EXP; ++c) sr[c] = 0.0f;
        for (int t = 0; t < TOPK; ++t) {
            sr[sidx[t]] = expf(sval[t] - mx) * inv;
            idxf[grow * TOPK + t] = (float)sidx[t];
        }
    }
}

extern "C" void kernel_launch(void* const* d_in, const int* in_sizes, int n_in,
                              void* d_out, int out_size)
{
    const float* x = (const float*)d_in[0];
    const float* W = (const float*)d_in[1];
    const float* b = (const float*)d_in[2];

    const int M = in_sizes[0] / HDIM;     // 16384

    float* out    = (float*)d_out;
    float* sparse = out;
    float* idxf   = out + (long long)M * EXP;
    float* gate   = out + (long long)M * EXP + (long long)M * TOPK;

    wfrag_kernel<<<(NFRAG + 255) / 256, 256>>>(W);
    gating_fused<<<M / CTAROWS, THREADS, SMEM_SZ>>>(x, b, sparse, idxf, gate);
}

// round 16
// speedup vs baseline: 1.0262x; 1.0075x over previous
#include <cuda_runtime.h>
#include <cuda_fp16.h>
#include <math.h>
#include <stdint.h>

#define HDIM    4096
#define EXP     64
#define TOPK    8
#define CTAROWS 64
#define THREADS 256
#define KC      32
#define NCHUNK  (HDIM / KC)      // 128
#define FOLD    4
#define WSCALE  64.0f
#define WINV    (1.0f / 64.0f)

// SMEM: double-buffered A tiles (fp16x2, 64 rows x 32k, 80B stride) + bias.
#define OFF_BIAS 0
#define OFF_A    256
#define A_LVL    (CTAROWS * 80)          // 5120
#define A_STG    (2 * A_LVL)             // 10240
#define SMEM_SZ  (OFF_A + 2 * A_STG)     // 20736
#define OFF_LOG  OFF_A                   // 64*66*4 = 16896 fits in 20480
#define LOGSTR   66

// W (x64) in B-fragment order: [chunk][ks][lvb(2)][nt(8)][lane(32)] -> uint2{b0,b1}
#define NFRAG (NCHUNK * 2 * 2 * 8 * 32)
__device__ uint2 g_wfrag[NFRAG];

// ---------------- helpers ----------------
static __device__ __forceinline__ uint32_t smem_u32(const void* p) {
    uint32_t a;
    asm("{ .reg .u64 t; cvta.to.shared.u64 t, %1; cvt.u32.u64 %0, t; }"
        : "=r"(a) : "l"(p));
    return a;
}
// split fp32 pair -> 2 packed fp16x2 words (a ~= h0 + h1, residual ~2^-22)
static __device__ __forceinline__ void split2h(float a0, float a1,
                                               uint32_t& u0, uint32_t& u1) {
    __half h0x = __float2half_rn(a0), h0y = __float2half_rn(a1);
    float r0 = a0 - __half2float(h0x);
    float r1 = a1 - __half2float(h0y);
    __half h1x = __float2half_rn(r0), h1y = __float2half_rn(r1);
    __half2 p0 = __halves2half2(h0x, h0y);
    __half2 p1 = __halves2half2(h1x, h1y);
    u0 = *reinterpret_cast<uint32_t*>(&p0);
    u1 = *reinterpret_cast<uint32_t*>(&p1);
}
static __device__ __forceinline__ void ldsm4(uint32_t* r, uint32_t addr) {
    asm volatile("ldmatrix.sync.aligned.m8n8.x4.shared.b16 {%0,%1,%2,%3}, [%4];"
                 : "=r"(r[0]), "=r"(r[1]), "=r"(r[2]), "=r"(r[3]) : "r"(addr));
}
static __device__ __forceinline__ void mma16816(float* c, const uint32_t* a,
                                                const uint32_t* b) {
    asm volatile(
        "mma.sync.aligned.m16n8k16.row.col.f32.f16.f16.f32 "
        "{%0,%1,%2,%3}, {%4,%5,%6,%7}, {%8,%9}, {%0,%1,%2,%3};"
        : "+f"(c[0]), "+f"(c[1]), "+f"(c[2]), "+f"(c[3])
        : "r"(a[0]), "r"(a[1]), "r"(a[2]), "r"(a[3]), "r"(b[0]), "r"(b[1]));
}

// ---------------- W repack: fp32*64 -> fp16x2 B-fragments ----------------
__global__ void wfrag_kernel(const float* __restrict__ W) {
    int idx = blockIdx.x * blockDim.x + threadIdx.x;
    if (idx >= NFRAG) return;
    int lane = idx & 31;
    int nt   = (idx >> 5) & 7;
    int t    = idx >> 8;
    int lvb  = t & 1;
    int ks   = (t >> 1) & 1;
    int ch   = t >> 2;
    int e = nt * 8 + (lane >> 2);
    int k = ch * KC + ks * 16 + (lane & 3) * 2;
    const float* w = W + (long long)e * HDIM + k;
    uint32_t u0a, u1a, u0b, u1b;
    split2h(w[0] * WSCALE, w[1] * WSCALE, u0a, u1a);
    split2h(w[8] * WSCALE, w[9] * WSCALE, u0b, u1b);
    uint2 v;
    v.x = lvb ? u1a : u0a;
    v.y = lvb ? u1b : u0b;
    g_wfrag[idx] = v;
}

// ---------------- fused gating ----------------
__global__ __launch_bounds__(THREADS, 2)
void gating_fused(const float* __restrict__ x, const float* __restrict__ b,
                  float* __restrict__ sparse, float* __restrict__ idxf,
                  float* __restrict__ gate)
{
    extern __shared__ char smem[];
    const uint32_t sb = smem_u32(smem);
    const int tid  = threadIdx.x;
    const int warp = tid >> 5;
    const int lane = tid & 31;
    const int rg = warp & 1;      // rows rg*32..+32
    const int eg = warp >> 1;     // experts eg*16..+16 (nt tiles 2eg, 2eg+1)
    const long long row_base = (long long)blockIdx.x * CTAROWS;

    if (tid < EXP) ((float*)(smem + OFF_BIAS))[tid] = b[tid];

    const float4* __restrict__ x4 = reinterpret_cast<const float4*>(x);

    const uint32_t a_lane = (uint32_t)((lane & 15) * 80 + (lane >> 4) * 16);
    const uint32_t a_base = sb + OFF_A + (uint32_t)rg * (32 * 80) + a_lane;

    float acc[16], sum[16];
#pragma unroll
    for (int i = 0; i < 16; ++i) { acc[i] = 0.f; sum[i] = 0.f; }

    // ---- prologue: load + convert chunk 0 into stage 0 ----
    float4 xr[2];
#pragma unroll
    for (int j = 0; j < 2; ++j) {
        int f = j * 256 + tid, r = f >> 3, q = f & 7;
        xr[j] = x4[(row_base + r) * (HDIM / 4) + q];
    }
#pragma unroll
    for (int j = 0; j < 2; ++j) {
        int f = j * 256 + tid, r = f >> 3, q = f & 7;
        uint2 v0, v1;
        split2h(xr[j].x, xr[j].y, v0.x, v1.x);
        split2h(xr[j].z, xr[j].w, v0.y, v1.y);
        uint32_t so = (uint32_t)(r * 80 + q * 8);
        *(uint2*)(smem + OFF_A + 0 * A_LVL + so) = v0;
        *(uint2*)(smem + OFF_A + 1 * A_LVL + so) = v1;
    }

    // B fragment double buffer; preload (chunk0, ks0, lvb0)
    uint2 bf[2][2];
    {
        const uint2* p0 = g_wfrag + (long long)(eg * 2) * 32 + lane;
        bf[0][0] = p0[0];
        bf[0][1] = p0[32];
    }
    int pp = 0;

    __syncthreads();

    for (int i = 0; i < NCHUNK; ++i) {
        const int stg = i & 1;
        const uint32_t a_st = a_base + (uint32_t)stg * A_STG;

        // ---- prefetch x for chunk i+1 ----
        if (i + 1 < NCHUNK) {
#pragma unroll
            for (int j = 0; j < 2; ++j) {
                int f = j * 256 + tid, r = f >> 3, q = f & 7;
                xr[j] = x4[(row_base + r) * (HDIM / 4) + (i + 1) * 8 + q];
            }
        }

        // ---- compute: per ks, 3 passes (b0c0, b1c0, b0c1) ----
#pragma unroll
        for (int ks = 0; ks < 2; ++ks) {
            uint32_t afr[2][2][4];
#pragma unroll
            for (int lv = 0; lv < 2; ++lv)
#pragma unroll
                for (int mt = 0; mt < 2; ++mt)
                    ldsm4(afr[lv][mt], a_st + lv * A_LVL + mt * (16 * 80) + ks * 32);

            // prefetch (i, ks, lvb=1)
            {
                const uint2* np = g_wfrag +
                    ((long long)(((i * 2 + ks) * 2 + 1) * 8 + eg * 2) * 32) + lane;
                bf[pp ^ 1][0] = np[0];
                bf[pp ^ 1][1] = np[32];
            }
            // passes with B level 0: A levels 0 and 1 (b0c0 + b1c0)
#pragma unroll
            for (int ap = 0; ap < 2; ++ap)
#pragma unroll
                for (int mt = 0; mt < 2; ++mt)
#pragma unroll
                    for (int nt = 0; nt < 2; ++nt)
                        mma16816(&acc[(mt * 2 + nt) * 4], afr[ap][mt],
                                 (const uint32_t*)&bf[pp][nt]);
            pp ^= 1;

            // prefetch next stage's lvb0: (i, ks+1) or (i+1, 0)
            {
                int nch = i, nks = ks + 1;
                if (nks == 2) { nks = 0; nch = (i + 1 < NCHUNK) ? i + 1 : i; }
                const uint2* np = g_wfrag +
                    ((long long)(((nch * 2 + nks) * 2 + 0) * 8 + eg * 2) * 32) + lane;
                bf[pp ^ 1][0] = np[0];
                bf[pp ^ 1][1] = np[32];
            }
            // pass with B level 1: A level 0 (b0c1)
#pragma unroll
            for (int mt = 0; mt < 2; ++mt)
#pragma unroll
                for (int nt = 0; nt < 2; ++nt)
                    mma16816(&acc[(mt * 2 + nt) * 4], afr[0][mt],
                             (const uint32_t*)&bf[pp][nt]);
            pp ^= 1;
        }

        // ---- convert chunk i+1 into the other stage ----
        if (i + 1 < NCHUNK) {
            const uint32_t dst = OFF_A + (uint32_t)(stg ^ 1) * A_STG;
#pragma unroll
            for (int j = 0; j < 2; ++j) {
                int f = j * 256 + tid, r = f >> 3, q = f & 7;
                uint2 v0, v1;
                split2h(xr[j].x, xr[j].y, v0.x, v1.x);
                split2h(xr[j].z, xr[j].w, v0.y, v1.y);
                uint32_t so = (uint32_t)(r * 80 + q * 8);
                *(uint2*)(smem + dst + 0 * A_LVL + so) = v0;
                *(uint2*)(smem + dst + 1 * A_LVL + so) = v1;
            }
        }

        // ---- fold into fp32 master (bounds HMMA chain bias) ----
        if ((i & (FOLD - 1)) == (FOLD - 1)) {
#pragma unroll
            for (int q = 0; q < 16; ++q) { sum[q] += acc[q]; acc[q] = 0.f; }
        }

        __syncthreads();
    }

    // ---- write logits to SMEM (undo W scale) ----
    {
        float* lg = (float*)(smem + OFF_LOG);
#pragma unroll
        for (int mt = 0; mt < 2; ++mt) {
            int r0 = rg * 32 + mt * 16 + (lane >> 2);
#pragma unroll
            for (int nt = 0; nt < 2; ++nt) {
                int col = eg * 16 + nt * 8 + (lane & 3) * 2;
                int a0 = (mt * 2 + nt) * 4;
                float t0 = (sum[a0 + 0] + acc[a0 + 0]) * WINV;
                float t1 = (sum[a0 + 1] + acc[a0 + 1]) * WINV;
                float t2 = (sum[a0 + 2] + acc[a0 + 2]) * WINV;
                float t3 = (sum[a0 + 3] + acc[a0 + 3]) * WINV;
                *(float2*)&lg[r0 * LOGSTR + col]       = make_float2(t0, t1);
                *(float2*)&lg[(r0 + 8) * LOGSTR + col] = make_float2(t2, t3);
            }
        }
    }
    __syncthreads();

    // ---- per-row epilogue: bias + gate + top-8 + masked softmax ----
    if (tid < CTAROWS) {
        const float* lg = (const float*)(smem + OFF_LOG) + tid * LOGSTR;
        const float* bs = (const float*)(smem + OFF_BIAS);
        float v[EXP];
#pragma unroll
        for (int c = 0; c < EXP; ++c) v[c] = lg[c] + bs[c];

        const long long grow = row_base + tid;
        float* gr = gate + grow * EXP;
#pragma unroll
        for (int c = 0; c < 16; ++c)
            ((float4*)gr)[c] = make_float4(v[4*c], v[4*c+1], v[4*c+2], v[4*c+3]);

        unsigned long long mask = 0ull;
        float sval[TOPK]; int sidx[TOPK];
        for (int t = 0; t < TOPK; ++t) {
            float best = -INFINITY; int bi = 0;
#pragma unroll
            for (int c = 0; c < EXP; ++c) {
                bool fr = !((mask >> c) & 1ull);
                if (fr && v[c] > best) { best = v[c]; bi = c; }   // tie -> lower idx
            }
            mask |= 1ull << bi;
            sval[t] = best; sidx[t] = bi;
        }
        float mx = sval[0], sumv = 0.f;
#pragma unroll
        for (int t = 0; t < TOPK; ++t) sumv += expf(sval[t] - mx);
        float inv = 1.0f / sumv;

        float* sr = sparse + grow * EXP;
#pragma unroll
        for (int c = 0; c < EXP; ++c) sr[c] = 0.0f;
        for (int t = 0; t < TOPK; ++t) {
            sr[sidx[t]] = expf(sval[t] - mx) * inv;
            idxf[grow * TOPK + t] = (float)sidx[t];
        }
    }
}

extern "C" void kernel_launch(void* const* d_in, const int* in_sizes, int n_in,
                              void* d_out, int out_size)
{
    const float* x = (const float*)d_in[0];
    const float* W = (const float*)d_in[1];
    const float* b = (const float*)d_in[2];

    const int M = in_sizes[0] / HDIM;     // 16384

    float* out    = (float*)d_out;
    float* sparse = out;
    float* idxf   = out + (long long)M * EXP;
    float* gate   = out + (long long)M * EXP + (long long)M * TOPK;

    wfrag_kernel<<<(NFRAG + 255) / 256, 256>>>(W);
    gating_fused<<<M / CTAROWS, THREADS, SMEM_SZ>>>(x, b, sparse, idxf, gate);
}